// round 7
// baseline (speedup 1.0000x reference)
#include <cuda_runtime.h>
#include <cuda_bf16.h>

// Problem constants (match reference_code)
#define N_NODES 50000
#define DIM     128
#define E_TOTAL 600000
#define ROW_BLOCKS ((N_NODES + 127) / 128)   // 391

// Projection tables (bf16: halves L2 gather traffic in the edge phase).
__device__ __nv_bfloat16 g_A[(size_t)N_NODES * DIM];
__device__ __nv_bfloat16 g_B[(size_t)N_NODES * DIM];
__device__ double g_loss_sum;
__device__ unsigned g_done = 0;

// cvt.rn.bf16x2.f32 d, a, b  -> d = {hi=a, lo=b}
__device__ __forceinline__ unsigned cvt2(float hi, float lo) {
    unsigned r; asm("cvt.rn.bf16x2.f32 %0, %1, %2;" : "=r"(r) : "f"(hi), "f"(lo)); return r;
}
__device__ __forceinline__ uint2 cvt4(float4 v) {
    return make_uint2(cvt2(v.y, v.x), cvt2(v.w, v.z));
}

__device__ __forceinline__ void ldsm_x4(unsigned* r, unsigned addr) {
    asm volatile("ldmatrix.sync.aligned.m8n8.x4.shared.b16 {%0,%1,%2,%3}, [%4];"
                 : "=r"(r[0]), "=r"(r[1]), "=r"(r[2]), "=r"(r[3]) : "r"(addr));
}

__device__ __forceinline__ void mma_bf16(float* c, const unsigned* a, unsigned b0, unsigned b1) {
    asm volatile("mma.sync.aligned.m16n8k16.row.col.f32.bf16.bf16.f32 "
                 "{%0,%1,%2,%3}, {%4,%5,%6,%7}, {%8,%9}, {%0,%1,%2,%3};"
                 : "+f"(c[0]), "+f"(c[1]), "+f"(c[2]), "+f"(c[3])
                 : "r"(a[0]), "r"(a[1]), "r"(a[2]), "r"(a[3]), "r"(b0), "r"(b1));
}

// ---------------------------------------------------------------------------
// Kernel 1: fused node projection GEMM (both halves per block).
// Block: 128 rows x 256 cols, 512 threads = 16 warps (warp_m=w&3: 32 rows,
// warp_n=w>>2: 64 cols; warp_n<2 -> A-half (+b1), warp_n>=2 -> B-half).
// x and W1 read as fp32 and converted to bf16 in-register while staging
// (x read ONCE per block; W1 is L2-resident).
// K chunked by 32; smem pitch 40 bf16 (80B rows) -> conflict-free ldmatrix.
// ---------------------------------------------------------------------------
#define PITCH 40
__global__ __launch_bounds__(512) void gemm_kernel(
    const float* __restrict__ x,    // [N_NODES, 128]
    const float* __restrict__ W1,   // [128, 256] row-major
    const float* __restrict__ b1)   // [128]
{
    const int row0 = blockIdx.x * 128;
    const int tid  = threadIdx.x;
    const int lane = tid & 31;
    const int w    = tid >> 5;
    const int warp_m = w & 3;
    const int warp_n = w >> 2;

    if (blockIdx.x == 0 && tid == 0) g_loss_sum = 0.0;

    __shared__ __nv_bfloat16 As[128 * PITCH];   // x rows, current 32-k chunk
    __shared__ __nv_bfloat16 Bs[256 * PITCH];   // output-col rows (0-127: A half W, 128-255: B half W)

    float acc[2][8][4];
#pragma unroll
    for (int mt = 0; mt < 2; mt++)
#pragma unroll
        for (int nt = 0; nt < 8; nt++)
#pragma unroll
            for (int q = 0; q < 4; q++) acc[mt][nt][q] = 0.0f;

    // ldmatrix lane base addresses (byte offsets into shared space).
    unsigned a_base = (unsigned)__cvta_generic_to_shared(As)
        + (unsigned)(((32 * warp_m + (lane & 15)) * PITCH + (lane >> 4) * 8) * 2);
    unsigned b_base = (unsigned)__cvta_generic_to_shared(Bs)
        + (unsigned)(((64 * warp_n + (lane & 7) + ((lane >> 4) << 3)) * PITCH
                      + ((lane >> 3) & 1) * 8) * 2);

    for (int kc = 0; kc < 128; kc += 32) {
        // Stage x chunk: 128 rows x 32 k = 1024 float4 reads -> bf16.
#pragma unroll
        for (int i = tid; i < 1024; i += 512) {
            int r = i >> 3, c = i & 7;
            int row = row0 + r;
            float4 v = (row < N_NODES) ? *(const float4*)(x + (size_t)row * 128 + kc + c * 4)
                                       : make_float4(0.f, 0.f, 0.f, 0.f);
            *(uint2*)(As + r * PITCH + c * 4) = cvt4(v);
        }
        // Stage W chunk: 256 output rows x 32 k = 2048 float4 reads (L2) -> bf16.
        // Bs row jj: output col jj; j = jj&127, k-offset = (jj>>7)*128 + kc.
#pragma unroll
        for (int i = tid; i < 2048; i += 512) {
            int jj = i >> 3, c = i & 7;
            int j = jj & 127;
            int koff = ((jj >> 7) << 7) + kc + c * 4;
            float4 v = *(const float4*)(W1 + (size_t)j * 256 + koff);
            *(uint2*)(Bs + jj * PITCH + c * 4) = cvt4(v);
        }
        __syncthreads();

#pragma unroll
        for (int ks = 0; ks < 2; ks++) {
            unsigned a0[4], a1[4];
            ldsm_x4(a0, a_base + ks * 32);                       // m tile 0
            ldsm_x4(a1, a_base + 16 * PITCH * 2 + ks * 32);      // m tile 1 (+16 rows)
#pragma unroll
            for (int nt2 = 0; nt2 < 4; nt2++) {
                unsigned b[4];
                ldsm_x4(b, b_base + nt2 * 16 * PITCH * 2 + ks * 32);
                mma_bf16(acc[0][2 * nt2],     a0, b[0], b[1]);
                mma_bf16(acc[1][2 * nt2],     a1, b[0], b[1]);
                mma_bf16(acc[0][2 * nt2 + 1], a0, b[2], b[3]);
                mma_bf16(acc[1][2 * nt2 + 1], a1, b[2], b[3]);
            }
        }
        __syncthreads();
    }

    // Epilogue: bias (A-half warps only), pack to bf16x2, store.
    const int g = lane >> 2, t = lane & 3;
    const int col_base = (warp_n & 1) * 64;
    __nv_bfloat16* __restrict__ out = (warp_n >= 2) ? g_B : g_A;

    float2 bias[8];
#pragma unroll
    for (int nt = 0; nt < 8; nt++) bias[nt] = make_float2(0.0f, 0.0f);
    if (warp_n < 2) {
#pragma unroll
        for (int nt = 0; nt < 8; nt++)
            bias[nt] = *(const float2*)(b1 + col_base + 8 * nt + 2 * t);
    }

#pragma unroll
    for (int mt = 0; mt < 2; mt++) {
        int row_lo = row0 + 32 * warp_m + 16 * mt + g;
        int row_hi = row_lo + 8;
#pragma unroll
        for (int nt = 0; nt < 8; nt++) {
            const float* c = acc[mt][nt];
            int col = col_base + 8 * nt + 2 * t;
            if (row_lo < N_NODES)
                *(unsigned*)(out + (size_t)row_lo * DIM + col) =
                    cvt2(c[1] + bias[nt].y, c[0] + bias[nt].x);
            if (row_hi < N_NODES)
                *(unsigned*)(out + (size_t)row_hi * DIM + col) =
                    cvt2(c[3] + bias[nt].y, c[2] + bias[nt].x);
        }
    }
}

// ---------------------------------------------------------------------------
// Kernel 2: edge phase + fused finalize. One warp per edge (grid-stride);
// bf16 tables are L2-resident (25.6MB) -> 307MB gather, L2-bound.
// Last block to finish writes the mean loss (and resets the counter so
// graph replays stay deterministic).
// pairs is int32 (JAX x64 disabled downcasts the reference's int64).
// ---------------------------------------------------------------------------
__global__ __launch_bounds__(256) void edge_kernel(
    const int*   __restrict__ pairs,   // [2, E] int32
    const float* __restrict__ labels,  // [E]
    const float* __restrict__ W2,      // [128]
    const float* __restrict__ b2,      // [1]
    float* __restrict__ out)           // [1]
{
    const int lane = threadIdx.x & 31;
    const int warp_global = (blockIdx.x * blockDim.x + threadIdx.x) >> 5;
    const int nwarps = (gridDim.x * blockDim.x) >> 5;

    const float4 w2 = ((const float4*)W2)[lane];  // cols 4*lane..4*lane+3
    const float bias2 = b2[0];

    float acc = 0.0f;

    for (int e = warp_global; e < E_TOTAL; e += nwarps) {
        int u = pairs[e];
        int v = pairs[E_TOTAL + e];
        uint2 av = *(const uint2*)(g_A + (size_t)u * DIM + 4 * lane);
        uint2 bv = *(const uint2*)(g_B + (size_t)v * DIM + 4 * lane);

        float2 a0 = __bfloat1622float2(*(const __nv_bfloat162*)&av.x);
        float2 a1 = __bfloat1622float2(*(const __nv_bfloat162*)&av.y);
        float2 b0 = __bfloat1622float2(*(const __nv_bfloat162*)&bv.x);
        float2 b1 = __bfloat1622float2(*(const __nv_bfloat162*)&bv.y);

        float z;
        z = fmaxf(a0.x + b0.x, 0.0f) * w2.x;
        z = fmaf(fmaxf(a0.y + b0.y, 0.0f), w2.y, z);
        z = fmaf(fmaxf(a1.x + b1.x, 0.0f), w2.z, z);
        z = fmaf(fmaxf(a1.y + b1.y, 0.0f), w2.w, z);

#pragma unroll
        for (int off = 16; off; off >>= 1)
            z += __shfl_xor_sync(0xFFFFFFFFu, z, off);
        z += bias2;

        float y = labels[e];
        float loss = fmaxf(z, 0.0f) - z * y + log1pf(expf(-fabsf(z)));
        acc += loss;
    }

    __shared__ float wsum[8];
    if (lane == 0) wsum[threadIdx.x >> 5] = acc;
    __syncthreads();
    if (threadIdx.x == 0) {
        float s = 0.0f;
#pragma unroll
        for (int i = 0; i < 8; i++) s += wsum[i];
        atomicAdd(&g_loss_sum, (double)s);
        __threadfence();
        if (atomicAdd(&g_done, 1u) == gridDim.x - 1) {
            g_done = 0;  // reset for next graph replay
            out[0] = (float)(g_loss_sum / (double)E_TOTAL);
        }
    }
}

// ---------------------------------------------------------------------------
// kernel_launch — input order: x, W1, b1, W2, b2, labels, pairs
// ---------------------------------------------------------------------------
extern "C" void kernel_launch(void* const* d_in, const int* in_sizes, int n_in,
                              void* d_out, int out_size) {
    const float* x      = (const float*)d_in[0];
    const float* W1     = (const float*)d_in[1];
    const float* b1     = (const float*)d_in[2];
    const float* W2     = (const float*)d_in[3];
    const float* b2     = (const float*)d_in[4];
    const float* labels = (const float*)d_in[5];
    const int*   pairs  = (const int*)d_in[6];
    float* out = (float*)d_out;

    gemm_kernel<<<ROW_BLOCKS, 512>>>(x, W1, b1);

    edge_kernel<<<1184, 256>>>(pairs, labels, W2, b2, out);
}

// round 8
// speedup vs baseline: 1.7372x; 1.7372x over previous
#include <cuda_runtime.h>
#include <cuda_bf16.h>

// Problem constants (match reference_code)
#define N_NODES 50000
#define DIM     128
#define E_TOTAL 600000
#define ROW_BLOCKS ((N_NODES + 127) / 128)   // 391

// Projection tables (bf16: halves L2 gather traffic in the edge phase).
// 256B-aligned so uint4 row slices are 16B-aligned.
__device__ __align__(256) __nv_bfloat16 g_A[(size_t)N_NODES * DIM];
__device__ __align__(256) __nv_bfloat16 g_B[(size_t)N_NODES * DIM];
__device__ double g_loss_sum;
__device__ unsigned g_done = 0;

// cvt.rn.bf16x2.f32 d, a, b  -> d = {hi=a, lo=b}
__device__ __forceinline__ unsigned cvt2(float hi, float lo) {
    unsigned r; asm("cvt.rn.bf16x2.f32 %0, %1, %2;" : "=r"(r) : "f"(hi), "f"(lo)); return r;
}
__device__ __forceinline__ uint2 cvt4(float4 v) {
    return make_uint2(cvt2(v.y, v.x), cvt2(v.w, v.z));
}

__device__ __forceinline__ void ldsm_x4(unsigned* r, unsigned addr) {
    asm volatile("ldmatrix.sync.aligned.m8n8.x4.shared.b16 {%0,%1,%2,%3}, [%4];"
                 : "=r"(r[0]), "=r"(r[1]), "=r"(r[2]), "=r"(r[3]) : "r"(addr));
}

__device__ __forceinline__ void mma_bf16(float* c, const unsigned* a, unsigned b0, unsigned b1) {
    asm volatile("mma.sync.aligned.m16n8k16.row.col.f32.bf16.bf16.f32 "
                 "{%0,%1,%2,%3}, {%4,%5,%6,%7}, {%8,%9}, {%0,%1,%2,%3};"
                 : "+f"(c[0]), "+f"(c[1]), "+f"(c[2]), "+f"(c[3])
                 : "r"(a[0]), "r"(a[1]), "r"(a[2]), "r"(a[3]), "r"(b0), "r"(b1));
}

// ---------------------------------------------------------------------------
// Kernel 1: fused node projection GEMM (both halves per block).
// Block: 128 rows x 256 cols, 512 threads = 16 warps (warp_m=w&3: 32 rows,
// warp_n=w>>2: 64 cols; warp_n<2 -> A-half (+b1), warp_n>=2 -> B-half).
// x and W1 read fp32, converted to bf16 in-register while staging.
// K chunked by 32; smem pitch 40 bf16 (80B rows) -> conflict-free ldmatrix.
// ---------------------------------------------------------------------------
#define PITCH 40
__global__ __launch_bounds__(512) void gemm_kernel(
    const float* __restrict__ x,    // [N_NODES, 128]
    const float* __restrict__ W1,   // [128, 256] row-major
    const float* __restrict__ b1)   // [128]
{
    const int row0 = blockIdx.x * 128;
    const int tid  = threadIdx.x;
    const int lane = tid & 31;
    const int w    = tid >> 5;
    const int warp_m = w & 3;
    const int warp_n = w >> 2;

    if (blockIdx.x == 0 && tid == 0) g_loss_sum = 0.0;

    __shared__ __nv_bfloat16 As[128 * PITCH];
    __shared__ __nv_bfloat16 Bs[256 * PITCH];

    float acc[2][8][4];
#pragma unroll
    for (int mt = 0; mt < 2; mt++)
#pragma unroll
        for (int nt = 0; nt < 8; nt++)
#pragma unroll
            for (int q = 0; q < 4; q++) acc[mt][nt][q] = 0.0f;

    unsigned a_base = (unsigned)__cvta_generic_to_shared(As)
        + (unsigned)(((32 * warp_m + (lane & 15)) * PITCH + (lane >> 4) * 8) * 2);
    unsigned b_base = (unsigned)__cvta_generic_to_shared(Bs)
        + (unsigned)(((64 * warp_n + (lane & 7) + ((lane >> 4) << 3)) * PITCH
                      + ((lane >> 3) & 1) * 8) * 2);

    for (int kc = 0; kc < 128; kc += 32) {
#pragma unroll
        for (int i = tid; i < 1024; i += 512) {
            int r = i >> 3, c = i & 7;
            int row = row0 + r;
            float4 v = (row < N_NODES) ? *(const float4*)(x + (size_t)row * 128 + kc + c * 4)
                                       : make_float4(0.f, 0.f, 0.f, 0.f);
            *(uint2*)(As + r * PITCH + c * 4) = cvt4(v);
        }
#pragma unroll
        for (int i = tid; i < 2048; i += 512) {
            int jj = i >> 3, c = i & 7;
            int j = jj & 127;
            int koff = ((jj >> 7) << 7) + kc + c * 4;
            float4 v = *(const float4*)(W1 + (size_t)j * 256 + koff);
            *(uint2*)(Bs + jj * PITCH + c * 4) = cvt4(v);
        }
        __syncthreads();

#pragma unroll
        for (int ks = 0; ks < 2; ks++) {
            unsigned a0[4], a1[4];
            ldsm_x4(a0, a_base + ks * 32);
            ldsm_x4(a1, a_base + 16 * PITCH * 2 + ks * 32);
#pragma unroll
            for (int nt2 = 0; nt2 < 4; nt2++) {
                unsigned b[4];
                ldsm_x4(b, b_base + nt2 * 16 * PITCH * 2 + ks * 32);
                mma_bf16(acc[0][2 * nt2],     a0, b[0], b[1]);
                mma_bf16(acc[1][2 * nt2],     a1, b[0], b[1]);
                mma_bf16(acc[0][2 * nt2 + 1], a0, b[2], b[3]);
                mma_bf16(acc[1][2 * nt2 + 1], a1, b[2], b[3]);
            }
        }
        __syncthreads();
    }

    const int g = lane >> 2, t = lane & 3;
    const int col_base = (warp_n & 1) * 64;
    __nv_bfloat16* __restrict__ out = (warp_n >= 2) ? g_B : g_A;

    float2 bias[8];
#pragma unroll
    for (int nt = 0; nt < 8; nt++) bias[nt] = make_float2(0.0f, 0.0f);
    if (warp_n < 2) {
#pragma unroll
        for (int nt = 0; nt < 8; nt++)
            bias[nt] = *(const float2*)(b1 + col_base + 8 * nt + 2 * t);
    }

#pragma unroll
    for (int mt = 0; mt < 2; mt++) {
        int row_lo = row0 + 32 * warp_m + 16 * mt + g;
        int row_hi = row_lo + 8;
#pragma unroll
        for (int nt = 0; nt < 8; nt++) {
            const float* c = acc[mt][nt];
            int col = col_base + 8 * nt + 2 * t;
            if (row_lo < N_NODES)
                *(unsigned*)(out + (size_t)row_lo * DIM + col) =
                    cvt2(c[1] + bias[nt].y, c[0] + bias[nt].x);
            if (row_hi < N_NODES)
                *(unsigned*)(out + (size_t)row_hi * DIM + col) =
                    cvt2(c[3] + bias[nt].y, c[2] + bias[nt].x);
        }
    }
}

// ---------------------------------------------------------------------------
// Kernel 2: edge phase + fused finalize. EIGHT threads per edge (warp = 4
// edges): each thread owns 16 dims (2 x uint4 of bf16x2 per table). Packed
// bf16 add+relu (__hadd2/__hmax2), exact shl/and bf16->f32, fp32 FFMA dot.
// 3-shfl reduction within 8-lane groups; fast-math BCE tail once per group.
// pairs is int32 (JAX x64 disabled downcasts the reference's int64).
// ---------------------------------------------------------------------------
__device__ __forceinline__ void dot2(float& z0, float& z1,
                                     unsigned a, unsigned b, float w0, float w1) {
    __nv_bfloat162 av = *(__nv_bfloat162*)&a;
    __nv_bfloat162 bv = *(__nv_bfloat162*)&b;
    __nv_bfloat162 zz = __float2bfloat162_rn(0.0f);
    __nv_bfloat162 s  = __hmax2(__hadd2(av, bv), zz);
    unsigned r = *(unsigned*)&s;
    z0 = fmaf(__uint_as_float(r << 16),          w0, z0);  // lo element (exact cvt)
    z1 = fmaf(__uint_as_float(r & 0xFFFF0000u),  w1, z1);  // hi element (exact cvt)
}

__global__ __launch_bounds__(256) void edge_kernel(
    const int*   __restrict__ pairs,   // [2, E] int32
    const float* __restrict__ labels,  // [E]
    const float* __restrict__ W2,      // [128]
    const float* __restrict__ b2,      // [1]
    float* __restrict__ out)           // [1]
{
    const int lane = threadIdx.x & 31;
    const int sub  = lane & 7;                                   // lane within edge-group
    const int grp  = (blockIdx.x * blockDim.x + threadIdx.x) >> 3;
    const int ngroups = (gridDim.x * blockDim.x) >> 3;

    // This thread's 16-dim slice of W2: dims [16*sub, 16*sub+16).
    float4 wv[4];
#pragma unroll
    for (int q = 0; q < 4; q++) wv[q] = ((const float4*)W2)[4 * sub + q];
    const float* wf = (const float*)wv;
    const float bias2 = b2[0];

    float acc = 0.0f;

    for (int e = grp; e < E_TOTAL; e += ngroups) {
        int u = pairs[e];
        int v = pairs[E_TOTAL + e];
        const uint4* ap = (const uint4*)(g_A + (size_t)u * DIM + 16 * sub);
        const uint4* bp = (const uint4*)(g_B + (size_t)v * DIM + 16 * sub);
        uint4 a0 = ap[0], a1 = ap[1];
        uint4 b0 = bp[0], b1 = bp[1];

        float z0 = 0.0f, z1 = 0.0f;
        dot2(z0, z1, a0.x, b0.x, wf[0],  wf[1]);
        dot2(z0, z1, a0.y, b0.y, wf[2],  wf[3]);
        dot2(z0, z1, a0.z, b0.z, wf[4],  wf[5]);
        dot2(z0, z1, a0.w, b0.w, wf[6],  wf[7]);
        dot2(z0, z1, a1.x, b1.x, wf[8],  wf[9]);
        dot2(z0, z1, a1.y, b1.y, wf[10], wf[11]);
        dot2(z0, z1, a1.z, b1.z, wf[12], wf[13]);
        dot2(z0, z1, a1.w, b1.w, wf[14], wf[15]);
        float z = z0 + z1;

        // Reduce across the 8-lane group (xor<8 stays inside the group).
        z += __shfl_xor_sync(0xFFFFFFFFu, z, 4);
        z += __shfl_xor_sync(0xFFFFFFFFu, z, 2);
        z += __shfl_xor_sync(0xFFFFFFFFu, z, 1);
        z += bias2;

        // BCE tail (fast math): all 8 lanes compute identically; accumulate on sub==0.
        float y = labels[e];
        float p = __expf(-fabsf(z));
        float loss = fmaxf(z, 0.0f) - z * y + __logf(1.0f + p);
        if (sub == 0) acc += loss;
    }

    // Warp butterfly (once), then block reduce + fused finalize.
#pragma unroll
    for (int off = 16; off; off >>= 1)
        acc += __shfl_xor_sync(0xFFFFFFFFu, acc, off);

    __shared__ float wsum[8];
    if (lane == 0) wsum[threadIdx.x >> 5] = acc;
    __syncthreads();
    if (threadIdx.x == 0) {
        float s = 0.0f;
#pragma unroll
        for (int i = 0; i < 8; i++) s += wsum[i];
        atomicAdd(&g_loss_sum, (double)s);
        __threadfence();
        if (atomicAdd(&g_done, 1u) == gridDim.x - 1) {
            g_done = 0;  // reset for next graph replay
            out[0] = (float)(g_loss_sum / (double)E_TOTAL);
        }
    }
}

// ---------------------------------------------------------------------------
// kernel_launch — input order: x, W1, b1, W2, b2, labels, pairs
// ---------------------------------------------------------------------------
extern "C" void kernel_launch(void* const* d_in, const int* in_sizes, int n_in,
                              void* d_out, int out_size) {
    const float* x      = (const float*)d_in[0];
    const float* W1     = (const float*)d_in[1];
    const float* b1     = (const float*)d_in[2];
    const float* W2     = (const float*)d_in[3];
    const float* b2     = (const float*)d_in[4];
    const float* labels = (const float*)d_in[5];
    const int*   pairs  = (const int*)d_in[6];
    float* out = (float*)d_out;

    gemm_kernel<<<ROW_BLOCKS, 512>>>(x, W1, b1);

    edge_kernel<<<1184, 256>>>(pairs, labels, W2, b2, out);
}

// round 9
// speedup vs baseline: 1.8359x; 1.0568x over previous
#include <cuda_runtime.h>
#include <cuda_bf16.h>

// Problem constants (match reference_code)
#define N_NODES 50000
#define DIM     128
#define E_TOTAL 600000
#define ROW_BLOCKS ((N_NODES + 127) / 128)   // 391

// Projection tables (bf16: halves L2 gather traffic in the edge phase).
__device__ __align__(256) __nv_bfloat16 g_A[(size_t)N_NODES * DIM];
__device__ __align__(256) __nv_bfloat16 g_B[(size_t)N_NODES * DIM];
__device__ double g_loss_sum;
__device__ unsigned g_done = 0;

// cvt.rn.bf16x2.f32 d, a, b  -> d = {hi=a, lo=b}
__device__ __forceinline__ unsigned cvt2(float hi, float lo) {
    unsigned r; asm("cvt.rn.bf16x2.f32 %0, %1, %2;" : "=r"(r) : "f"(hi), "f"(lo)); return r;
}
__device__ __forceinline__ uint2 cvt4(float4 v) {
    return make_uint2(cvt2(v.y, v.x), cvt2(v.w, v.z));
}

__device__ __forceinline__ void ldsm_x4(unsigned* r, unsigned addr) {
    asm volatile("ldmatrix.sync.aligned.m8n8.x4.shared.b16 {%0,%1,%2,%3}, [%4];"
                 : "=r"(r[0]), "=r"(r[1]), "=r"(r[2]), "=r"(r[3]) : "r"(addr));
}

__device__ __forceinline__ void mma_bf16(float* c, const unsigned* a, unsigned b0, unsigned b1) {
    asm volatile("mma.sync.aligned.m16n8k16.row.col.f32.bf16.bf16.f32 "
                 "{%0,%1,%2,%3}, {%4,%5,%6,%7}, {%8,%9}, {%0,%1,%2,%3};"
                 : "+f"(c[0]), "+f"(c[1]), "+f"(c[2]), "+f"(c[3])
                 : "r"(a[0]), "r"(a[1]), "r"(a[2]), "r"(a[3]), "r"(b0), "r"(b1));
}

// ---------------------------------------------------------------------------
// Kernel 1: fused node projection GEMM (both halves per block).
// Block: 128 rows x 256 cols, 512 threads = 16 warps (warp_m=w&3: 32 rows,
// warp_n=w>>2: 64 cols; warp_n<2 -> A-half (+b1), warp_n>=2 -> B-half).
// x and W1 read fp32, converted to bf16 in-register while staging.
// K chunked by 32; smem pitch 40 bf16 (80B rows) -> conflict-free ldmatrix.
// ---------------------------------------------------------------------------
#define PITCH 40
__global__ __launch_bounds__(512) void gemm_kernel(
    const float* __restrict__ x,    // [N_NODES, 128]
    const float* __restrict__ W1,   // [128, 256] row-major
    const float* __restrict__ b1)   // [128]
{
    const int row0 = blockIdx.x * 128;
    const int tid  = threadIdx.x;
    const int lane = tid & 31;
    const int w    = tid >> 5;
    const int warp_m = w & 3;
    const int warp_n = w >> 2;

    if (blockIdx.x == 0 && tid == 0) g_loss_sum = 0.0;

    __shared__ __nv_bfloat16 As[128 * PITCH];
    __shared__ __nv_bfloat16 Bs[256 * PITCH];

    float acc[2][8][4];
#pragma unroll
    for (int mt = 0; mt < 2; mt++)
#pragma unroll
        for (int nt = 0; nt < 8; nt++)
#pragma unroll
            for (int q = 0; q < 4; q++) acc[mt][nt][q] = 0.0f;

    unsigned a_base = (unsigned)__cvta_generic_to_shared(As)
        + (unsigned)(((32 * warp_m + (lane & 15)) * PITCH + (lane >> 4) * 8) * 2);
    unsigned b_base = (unsigned)__cvta_generic_to_shared(Bs)
        + (unsigned)(((64 * warp_n + (lane & 7) + ((lane >> 4) << 3)) * PITCH
                      + ((lane >> 3) & 1) * 8) * 2);

    for (int kc = 0; kc < 128; kc += 32) {
#pragma unroll
        for (int i = tid; i < 1024; i += 512) {
            int r = i >> 3, c = i & 7;
            int row = row0 + r;
            float4 v = (row < N_NODES) ? *(const float4*)(x + (size_t)row * 128 + kc + c * 4)
                                       : make_float4(0.f, 0.f, 0.f, 0.f);
            *(uint2*)(As + r * PITCH + c * 4) = cvt4(v);
        }
#pragma unroll
        for (int i = tid; i < 2048; i += 512) {
            int jj = i >> 3, c = i & 7;
            int j = jj & 127;
            int koff = ((jj >> 7) << 7) + kc + c * 4;
            float4 v = *(const float4*)(W1 + (size_t)j * 256 + koff);
            *(uint2*)(Bs + jj * PITCH + c * 4) = cvt4(v);
        }
        __syncthreads();

#pragma unroll
        for (int ks = 0; ks < 2; ks++) {
            unsigned a0[4], a1[4];
            ldsm_x4(a0, a_base + ks * 32);
            ldsm_x4(a1, a_base + 16 * PITCH * 2 + ks * 32);
#pragma unroll
            for (int nt2 = 0; nt2 < 4; nt2++) {
                unsigned b[4];
                ldsm_x4(b, b_base + nt2 * 16 * PITCH * 2 + ks * 32);
                mma_bf16(acc[0][2 * nt2],     a0, b[0], b[1]);
                mma_bf16(acc[1][2 * nt2],     a1, b[0], b[1]);
                mma_bf16(acc[0][2 * nt2 + 1], a0, b[2], b[3]);
                mma_bf16(acc[1][2 * nt2 + 1], a1, b[2], b[3]);
            }
        }
        __syncthreads();
    }

    const int g = lane >> 2, t = lane & 3;
    const int col_base = (warp_n & 1) * 64;
    __nv_bfloat16* __restrict__ out = (warp_n >= 2) ? g_B : g_A;

    float2 bias[8];
#pragma unroll
    for (int nt = 0; nt < 8; nt++) bias[nt] = make_float2(0.0f, 0.0f);
    if (warp_n < 2) {
#pragma unroll
        for (int nt = 0; nt < 8; nt++)
            bias[nt] = *(const float2*)(b1 + col_base + 8 * nt + 2 * t);
    }

#pragma unroll
    for (int mt = 0; mt < 2; mt++) {
        int row_lo = row0 + 32 * warp_m + 16 * mt + g;
        int row_hi = row_lo + 8;
#pragma unroll
        for (int nt = 0; nt < 8; nt++) {
            const float* c = acc[mt][nt];
            int col = col_base + 8 * nt + 2 * t;
            if (row_lo < N_NODES)
                *(unsigned*)(out + (size_t)row_lo * DIM + col) =
                    cvt2(c[1] + bias[nt].y, c[0] + bias[nt].x);
            if (row_hi < N_NODES)
                *(unsigned*)(out + (size_t)row_hi * DIM + col) =
                    cvt2(c[3] + bias[nt].y, c[2] + bias[nt].x);
        }
    }
}

// ---------------------------------------------------------------------------
// Kernel 2: edge phase + fused finalize. Eight threads per edge, grid-stride
// loop UNROLLED x2 (edges e and e+ngroups per iteration) to double per-thread
// MLP — the kernel is gather-latency bound, not throughput bound.
// pairs is int32 (JAX x64 disabled downcasts the reference's int64).
// ---------------------------------------------------------------------------
__device__ __forceinline__ void dot2(float& z0, float& z1,
                                     unsigned a, unsigned b, float w0, float w1) {
    __nv_bfloat162 av = *(__nv_bfloat162*)&a;
    __nv_bfloat162 bv = *(__nv_bfloat162*)&b;
    __nv_bfloat162 zz = __float2bfloat162_rn(0.0f);
    __nv_bfloat162 s  = __hmax2(__hadd2(av, bv), zz);
    unsigned r = *(unsigned*)&s;
    z0 = fmaf(__uint_as_float(r << 16),          w0, z0);  // lo element (exact cvt)
    z1 = fmaf(__uint_as_float(r & 0xFFFF0000u),  w1, z1);  // hi element (exact cvt)
}

__device__ __forceinline__ float edge_dot(const uint4& a0, const uint4& a1,
                                          const uint4& b0, const uint4& b1,
                                          const float* wf) {
    float z0 = 0.0f, z1 = 0.0f;
    dot2(z0, z1, a0.x, b0.x, wf[0],  wf[1]);
    dot2(z0, z1, a0.y, b0.y, wf[2],  wf[3]);
    dot2(z0, z1, a0.z, b0.z, wf[4],  wf[5]);
    dot2(z0, z1, a0.w, b0.w, wf[6],  wf[7]);
    dot2(z0, z1, a1.x, b1.x, wf[8],  wf[9]);
    dot2(z0, z1, a1.y, b1.y, wf[10], wf[11]);
    dot2(z0, z1, a1.z, b1.z, wf[12], wf[13]);
    dot2(z0, z1, a1.w, b1.w, wf[14], wf[15]);
    return z0 + z1;
}

__global__ __launch_bounds__(256) void edge_kernel(
    const int*   __restrict__ pairs,   // [2, E] int32
    const float* __restrict__ labels,  // [E]
    const float* __restrict__ W2,      // [128]
    const float* __restrict__ b2,      // [1]
    float* __restrict__ out)           // [1]
{
    const int lane = threadIdx.x & 31;
    const int sub  = lane & 7;
    const int grp  = (blockIdx.x * blockDim.x + threadIdx.x) >> 3;
    const int ngroups = (gridDim.x * blockDim.x) >> 3;

    // This thread's 16-dim slice of W2: dims [16*sub, 16*sub+16).
    float4 wv[4];
#pragma unroll
    for (int q = 0; q < 4; q++) wv[q] = ((const float4*)W2)[4 * sub + q];
    const float* wf = (const float*)wv;
    const float bias2 = b2[0];

    float acc = 0.0f;

    int e = grp;
    for (; e + ngroups < E_TOTAL; e += 2 * ngroups) {
        const int e2 = e + ngroups;
        // Issue all index loads, then all 16 gather loads, before consuming.
        int u1 = pairs[e],            v1 = pairs[E_TOTAL + e];
        int u2 = pairs[e2],           v2 = pairs[E_TOTAL + e2];
        const uint4* ap1 = (const uint4*)(g_A + (size_t)u1 * DIM + 16 * sub);
        const uint4* bp1 = (const uint4*)(g_B + (size_t)v1 * DIM + 16 * sub);
        const uint4* ap2 = (const uint4*)(g_A + (size_t)u2 * DIM + 16 * sub);
        const uint4* bp2 = (const uint4*)(g_B + (size_t)v2 * DIM + 16 * sub);
        uint4 a10 = __ldg(ap1), a11 = __ldg(ap1 + 1);
        uint4 b10 = __ldg(bp1), b11 = __ldg(bp1 + 1);
        uint4 a20 = __ldg(ap2), a21 = __ldg(ap2 + 1);
        uint4 b20 = __ldg(bp2), b21 = __ldg(bp2 + 1);
        float y1 = labels[e];
        float y2 = labels[e2];

        float za = edge_dot(a10, a11, b10, b11, wf);
        float zb = edge_dot(a20, a21, b20, b21, wf);

        za += __shfl_xor_sync(0xFFFFFFFFu, za, 4);
        zb += __shfl_xor_sync(0xFFFFFFFFu, zb, 4);
        za += __shfl_xor_sync(0xFFFFFFFFu, za, 2);
        zb += __shfl_xor_sync(0xFFFFFFFFu, zb, 2);
        za += __shfl_xor_sync(0xFFFFFFFFu, za, 1);
        zb += __shfl_xor_sync(0xFFFFFFFFu, zb, 1);
        za += bias2;
        zb += bias2;

        float pa = __expf(-fabsf(za));
        float pb = __expf(-fabsf(zb));
        float la = fmaxf(za, 0.0f) - za * y1 + __logf(1.0f + pa);
        float lb = fmaxf(zb, 0.0f) - zb * y2 + __logf(1.0f + pb);
        if (sub == 0) acc += la + lb;
    }
    // Remainder (at most one edge per group).
    if (e < E_TOTAL) {
        int u = pairs[e], v = pairs[E_TOTAL + e];
        const uint4* ap = (const uint4*)(g_A + (size_t)u * DIM + 16 * sub);
        const uint4* bp = (const uint4*)(g_B + (size_t)v * DIM + 16 * sub);
        uint4 a0 = __ldg(ap), a1 = __ldg(ap + 1);
        uint4 b0 = __ldg(bp), b1 = __ldg(bp + 1);
        float y = labels[e];

        float z = edge_dot(a0, a1, b0, b1, wf);
        z += __shfl_xor_sync(0xFFFFFFFFu, z, 4);
        z += __shfl_xor_sync(0xFFFFFFFFu, z, 2);
        z += __shfl_xor_sync(0xFFFFFFFFu, z, 1);
        z += bias2;

        float p = __expf(-fabsf(z));
        float loss = fmaxf(z, 0.0f) - z * y + __logf(1.0f + p);
        if (sub == 0) acc += loss;
    }

    // Warp butterfly, block reduce, fused finalize.
#pragma unroll
    for (int off = 16; off; off >>= 1)
        acc += __shfl_xor_sync(0xFFFFFFFFu, acc, off);

    __shared__ float wsum[8];
    if (lane == 0) wsum[threadIdx.x >> 5] = acc;
    __syncthreads();
    if (threadIdx.x == 0) {
        float s = 0.0f;
#pragma unroll
        for (int i = 0; i < 8; i++) s += wsum[i];
        atomicAdd(&g_loss_sum, (double)s);
        __threadfence();
        if (atomicAdd(&g_done, 1u) == gridDim.x - 1) {
            g_done = 0;  // reset for next graph replay
            out[0] = (float)(g_loss_sum / (double)E_TOTAL);
        }
    }
}

// ---------------------------------------------------------------------------
// kernel_launch — input order: x, W1, b1, W2, b2, labels, pairs
// ---------------------------------------------------------------------------
extern "C" void kernel_launch(void* const* d_in, const int* in_sizes, int n_in,
                              void* d_out, int out_size) {
    const float* x      = (const float*)d_in[0];
    const float* W1     = (const float*)d_in[1];
    const float* b1     = (const float*)d_in[2];
    const float* W2     = (const float*)d_in[3];
    const float* b2     = (const float*)d_in[4];
    const float* labels = (const float*)d_in[5];
    const int*   pairs  = (const int*)d_in[6];
    float* out = (float*)d_out;

    gemm_kernel<<<ROW_BLOCKS, 512>>>(x, W1, b1);

    edge_kernel<<<1184, 256>>>(pairs, labels, W2, b2, out);
}

// round 10
// speedup vs baseline: 1.9895x; 1.0837x over previous
#include <cuda_runtime.h>
#include <cuda_bf16.h>
#include <cuda_fp16.h>

// Problem constants (match reference_code)
#define N_NODES 50000
#define DIM     128
#define E_TOTAL 600000
#define ROW_BLOCKS ((N_NODES + 127) / 128)   // 391

// Projection tables in fp8 e4m3: quarters the edge-phase gather traffic vs
// fp32 (12.8MB total, fully L2-resident -> 154MB gather).
__device__ __align__(256) unsigned char g_A8[(size_t)N_NODES * DIM];
__device__ __align__(256) unsigned char g_B8[(size_t)N_NODES * DIM];
__device__ double g_loss_sum;
__device__ unsigned g_done = 0;

// cvt.rn.bf16x2.f32 d, a, b  -> d = {hi=a, lo=b}
__device__ __forceinline__ unsigned cvt2(float hi, float lo) {
    unsigned r; asm("cvt.rn.bf16x2.f32 %0, %1, %2;" : "=r"(r) : "f"(hi), "f"(lo)); return r;
}
__device__ __forceinline__ uint2 cvt4(float4 v) {
    return make_uint2(cvt2(v.y, v.x), cvt2(v.w, v.z));
}
// Pack two f32 -> e4m3x2 (16-bit; 'hi' lands in upper byte).
__device__ __forceinline__ unsigned short cvt_e4m3x2(float hi, float lo) {
    unsigned short r;
    asm("cvt.rn.satfinite.e4m3x2.f32 %0, %1, %2;" : "=h"(r) : "f"(hi), "f"(lo));
    return r;
}
// Unpack e4m3x2 -> half2 (lower e4m3 -> lower half).
__device__ __forceinline__ __half2 cvt_h2(unsigned short s) {
    unsigned r;
    asm("cvt.rn.f16x2.e4m3x2 %0, %1;" : "=r"(r) : "h"(s));
    return *(__half2*)&r;
}

__device__ __forceinline__ void ldsm_x4(unsigned* r, unsigned addr) {
    asm volatile("ldmatrix.sync.aligned.m8n8.x4.shared.b16 {%0,%1,%2,%3}, [%4];"
                 : "=r"(r[0]), "=r"(r[1]), "=r"(r[2]), "=r"(r[3]) : "r"(addr));
}

__device__ __forceinline__ void mma_bf16(float* c, const unsigned* a, unsigned b0, unsigned b1) {
    asm volatile("mma.sync.aligned.m16n8k16.row.col.f32.bf16.bf16.f32 "
                 "{%0,%1,%2,%3}, {%4,%5,%6,%7}, {%8,%9}, {%0,%1,%2,%3};"
                 : "+f"(c[0]), "+f"(c[1]), "+f"(c[2]), "+f"(c[3])
                 : "r"(a[0]), "r"(a[1]), "r"(a[2]), "r"(a[3]), "r"(b0), "r"(b1));
}

// ---------------------------------------------------------------------------
// Kernel 1: fused node projection GEMM (both halves per block).
// Block: 128 rows x 256 cols, 512 threads = 16 warps (warp_m=w&3: 32 rows,
// warp_n=w>>2: 64 cols; warp_n<2 -> A-half (+b1), warp_n>=2 -> B-half).
// x and W1 read fp32, converted to bf16 in-register while staging.
// K chunked by 32; smem pitch 40 bf16 (80B rows) -> conflict-free ldmatrix.
// Epilogue quantizes to e4m3.
// ---------------------------------------------------------------------------
#define PITCH 40
__global__ __launch_bounds__(512) void gemm_kernel(
    const float* __restrict__ x,    // [N_NODES, 128]
    const float* __restrict__ W1,   // [128, 256] row-major
    const float* __restrict__ b1)   // [128]
{
    const int row0 = blockIdx.x * 128;
    const int tid  = threadIdx.x;
    const int lane = tid & 31;
    const int w    = tid >> 5;
    const int warp_m = w & 3;
    const int warp_n = w >> 2;

    if (blockIdx.x == 0 && tid == 0) g_loss_sum = 0.0;

    __shared__ __nv_bfloat16 As[128 * PITCH];
    __shared__ __nv_bfloat16 Bs[256 * PITCH];

    float acc[2][8][4];
#pragma unroll
    for (int mt = 0; mt < 2; mt++)
#pragma unroll
        for (int nt = 0; nt < 8; nt++)
#pragma unroll
            for (int q = 0; q < 4; q++) acc[mt][nt][q] = 0.0f;

    unsigned a_base = (unsigned)__cvta_generic_to_shared(As)
        + (unsigned)(((32 * warp_m + (lane & 15)) * PITCH + (lane >> 4) * 8) * 2);
    unsigned b_base = (unsigned)__cvta_generic_to_shared(Bs)
        + (unsigned)(((64 * warp_n + (lane & 7) + ((lane >> 4) << 3)) * PITCH
                      + ((lane >> 3) & 1) * 8) * 2);

    for (int kc = 0; kc < 128; kc += 32) {
#pragma unroll
        for (int i = tid; i < 1024; i += 512) {
            int r = i >> 3, c = i & 7;
            int row = row0 + r;
            float4 v = (row < N_NODES) ? *(const float4*)(x + (size_t)row * 128 + kc + c * 4)
                                       : make_float4(0.f, 0.f, 0.f, 0.f);
            *(uint2*)(As + r * PITCH + c * 4) = cvt4(v);
        }
#pragma unroll
        for (int i = tid; i < 2048; i += 512) {
            int jj = i >> 3, c = i & 7;
            int j = jj & 127;
            int koff = ((jj >> 7) << 7) + kc + c * 4;
            float4 v = *(const float4*)(W1 + (size_t)j * 256 + koff);
            *(uint2*)(Bs + jj * PITCH + c * 4) = cvt4(v);
        }
        __syncthreads();

#pragma unroll
        for (int ks = 0; ks < 2; ks++) {
            unsigned a0[4], a1[4];
            ldsm_x4(a0, a_base + ks * 32);
            ldsm_x4(a1, a_base + 16 * PITCH * 2 + ks * 32);
#pragma unroll
            for (int nt2 = 0; nt2 < 4; nt2++) {
                unsigned b[4];
                ldsm_x4(b, b_base + nt2 * 16 * PITCH * 2 + ks * 32);
                mma_bf16(acc[0][2 * nt2],     a0, b[0], b[1]);
                mma_bf16(acc[1][2 * nt2],     a1, b[0], b[1]);
                mma_bf16(acc[0][2 * nt2 + 1], a0, b[2], b[3]);
                mma_bf16(acc[1][2 * nt2 + 1], a1, b[2], b[3]);
            }
        }
        __syncthreads();
    }

    const int g = lane >> 2, t = lane & 3;
    const int col_base = (warp_n & 1) * 64;
    unsigned char* __restrict__ out = (warp_n >= 2) ? g_B8 : g_A8;

    float2 bias[8];
#pragma unroll
    for (int nt = 0; nt < 8; nt++) bias[nt] = make_float2(0.0f, 0.0f);
    if (warp_n < 2) {
#pragma unroll
        for (int nt = 0; nt < 8; nt++)
            bias[nt] = *(const float2*)(b1 + col_base + 8 * nt + 2 * t);
    }

#pragma unroll
    for (int mt = 0; mt < 2; mt++) {
        int row_lo = row0 + 32 * warp_m + 16 * mt + g;
        int row_hi = row_lo + 8;
#pragma unroll
        for (int nt = 0; nt < 8; nt++) {
            const float* c = acc[mt][nt];
            int col = col_base + 8 * nt + 2 * t;
            if (row_lo < N_NODES)
                *(unsigned short*)(out + (size_t)row_lo * DIM + col) =
                    cvt_e4m3x2(c[1] + bias[nt].y, c[0] + bias[nt].x);
            if (row_hi < N_NODES)
                *(unsigned short*)(out + (size_t)row_hi * DIM + col) =
                    cvt_e4m3x2(c[3] + bias[nt].y, c[2] + bias[nt].x);
        }
    }
}

// ---------------------------------------------------------------------------
// Kernel 2: edge phase + fused finalize. Eight threads per edge, x2 unrolled
// grid-stride loop. fp8 tables: one uint4 gather per table per edge-thread.
// e4m3x2 -> f16x2 cvt, packed fp16 add+relu, hfma2 dot with half2 W2.
// pairs is int32 (JAX x64 disabled downcasts the reference's int64).
// ---------------------------------------------------------------------------
__device__ __forceinline__ float edge_dot8(uint4 a, uint4 b, const __half2* wh) {
    const unsigned* au = (const unsigned*)&a;
    const unsigned* bu = (const unsigned*)&b;
    __half2 acc = __float2half2_rn(0.0f);
    const __half2 z2 = __float2half2_rn(0.0f);
#pragma unroll
    for (int q = 0; q < 4; q++) {
        __half2 a0 = cvt_h2((unsigned short)(au[q] & 0xFFFFu));
        __half2 a1 = cvt_h2((unsigned short)(au[q] >> 16));
        __half2 b0 = cvt_h2((unsigned short)(bu[q] & 0xFFFFu));
        __half2 b1 = cvt_h2((unsigned short)(bu[q] >> 16));
        __half2 s0 = __hmax2(__hadd2(a0, b0), z2);
        __half2 s1 = __hmax2(__hadd2(a1, b1), z2);
        acc = __hfma2(s0, wh[2 * q],     acc);
        acc = __hfma2(s1, wh[2 * q + 1], acc);
    }
    return __low2float(acc) + __high2float(acc);
}

__global__ __launch_bounds__(256) void edge_kernel(
    const int*   __restrict__ pairs,   // [2, E] int32
    const float* __restrict__ labels,  // [E]
    const float* __restrict__ W2,      // [128]
    const float* __restrict__ b2,      // [1]
    float* __restrict__ out)           // [1]
{
    const int lane = threadIdx.x & 31;
    const int sub  = lane & 7;
    const int grp  = (blockIdx.x * blockDim.x + threadIdx.x) >> 3;
    const int ngroups = (gridDim.x * blockDim.x) >> 3;

    // This thread's 16-dim slice of W2 as half2 (dims [16*sub, 16*sub+16)).
    __half2 wh[8];
#pragma unroll
    for (int q = 0; q < 8; q++) {
        float2 p = ((const float2*)W2)[8 * sub + q];
        wh[q] = __float22half2_rn(p);
    }
    const float bias2 = b2[0];

    float acc = 0.0f;

    int e = grp;
    for (; e + ngroups < E_TOTAL; e += 2 * ngroups) {
        const int e2 = e + ngroups;
        int u1 = pairs[e],  v1 = pairs[E_TOTAL + e];
        int u2 = pairs[e2], v2 = pairs[E_TOTAL + e2];
        uint4 a1 = __ldg((const uint4*)(g_A8 + (size_t)u1 * DIM + 16 * sub));
        uint4 b1 = __ldg((const uint4*)(g_B8 + (size_t)v1 * DIM + 16 * sub));
        uint4 a2 = __ldg((const uint4*)(g_A8 + (size_t)u2 * DIM + 16 * sub));
        uint4 b2v = __ldg((const uint4*)(g_B8 + (size_t)v2 * DIM + 16 * sub));
        float y1 = labels[e];
        float y2 = labels[e2];

        float za = edge_dot8(a1, b1, wh);
        float zb = edge_dot8(a2, b2v, wh);

        za += __shfl_xor_sync(0xFFFFFFFFu, za, 4);
        zb += __shfl_xor_sync(0xFFFFFFFFu, zb, 4);
        za += __shfl_xor_sync(0xFFFFFFFFu, za, 2);
        zb += __shfl_xor_sync(0xFFFFFFFFu, zb, 2);
        za += __shfl_xor_sync(0xFFFFFFFFu, za, 1);
        zb += __shfl_xor_sync(0xFFFFFFFFu, zb, 1);
        za += bias2;
        zb += bias2;

        float pa = __expf(-fabsf(za));
        float pb = __expf(-fabsf(zb));
        float la = fmaxf(za, 0.0f) - za * y1 + __logf(1.0f + pa);
        float lb = fmaxf(zb, 0.0f) - zb * y2 + __logf(1.0f + pb);
        if (sub == 0) acc += la + lb;
    }
    if (e < E_TOTAL) {
        int u = pairs[e], v = pairs[E_TOTAL + e];
        uint4 a = __ldg((const uint4*)(g_A8 + (size_t)u * DIM + 16 * sub));
        uint4 b = __ldg((const uint4*)(g_B8 + (size_t)v * DIM + 16 * sub));
        float y = labels[e];

        float z = edge_dot8(a, b, wh);
        z += __shfl_xor_sync(0xFFFFFFFFu, z, 4);
        z += __shfl_xor_sync(0xFFFFFFFFu, z, 2);
        z += __shfl_xor_sync(0xFFFFFFFFu, z, 1);
        z += bias2;

        float p = __expf(-fabsf(z));
        float loss = fmaxf(z, 0.0f) - z * y + __logf(1.0f + p);
        if (sub == 0) acc += loss;
    }

    // Warp butterfly, block reduce, fused finalize.
#pragma unroll
    for (int off = 16; off; off >>= 1)
        acc += __shfl_xor_sync(0xFFFFFFFFu, acc, off);

    __shared__ float wsum[8];
    if (lane == 0) wsum[threadIdx.x >> 5] = acc;
    __syncthreads();
    if (threadIdx.x == 0) {
        float s = 0.0f;
#pragma unroll
        for (int i = 0; i < 8; i++) s += wsum[i];
        atomicAdd(&g_loss_sum, (double)s);
        __threadfence();
        if (atomicAdd(&g_done, 1u) == gridDim.x - 1) {
            g_done = 0;  // reset for next graph replay
            out[0] = (float)(g_loss_sum / (double)E_TOTAL);
        }
    }
}

// ---------------------------------------------------------------------------
// kernel_launch — input order: x, W1, b1, W2, b2, labels, pairs
// ---------------------------------------------------------------------------
extern "C" void kernel_launch(void* const* d_in, const int* in_sizes, int n_in,
                              void* d_out, int out_size) {
    const float* x      = (const float*)d_in[0];
    const float* W1     = (const float*)d_in[1];
    const float* b1     = (const float*)d_in[2];
    const float* W2     = (const float*)d_in[3];
    const float* b2     = (const float*)d_in[4];
    const float* labels = (const float*)d_in[5];
    const int*   pairs  = (const int*)d_in[6];
    float* out = (float*)d_out;

    gemm_kernel<<<ROW_BLOCKS, 512>>>(x, W1, b1);

    edge_kernel<<<1184, 256>>>(pairs, labels, W2, b2, out);
}

// round 11
// speedup vs baseline: 2.0845x; 1.0477x over previous
#include <cuda_runtime.h>
#include <cuda_bf16.h>
#include <cuda_fp16.h>

// Problem constants (match reference_code)
#define N_NODES 50000
#define DIM     128
#define E_TOTAL 600000
#define ROW_BLOCKS ((N_NODES + 127) / 128)   // 391

// Projection tables in fp8 e4m3 (12.8MB total, L2-resident -> 154MB gather).
__device__ __align__(256) unsigned char g_A8[(size_t)N_NODES * DIM];
__device__ __align__(256) unsigned char g_B8[(size_t)N_NODES * DIM];
__device__ double g_loss_sum;
__device__ unsigned g_done = 0;

// cvt.rn.bf16x2.f32 d, a, b  -> d = {hi=a, lo=b}
__device__ __forceinline__ unsigned cvt2(float hi, float lo) {
    unsigned r; asm("cvt.rn.bf16x2.f32 %0, %1, %2;" : "=r"(r) : "f"(hi), "f"(lo)); return r;
}
__device__ __forceinline__ uint2 cvt4(float4 v) {
    return make_uint2(cvt2(v.y, v.x), cvt2(v.w, v.z));
}
// Pack two f32 -> e4m3x2 (16-bit; 'hi' lands in upper byte).
__device__ __forceinline__ unsigned short cvt_e4m3x2(float hi, float lo) {
    unsigned short r;
    asm("cvt.rn.satfinite.e4m3x2.f32 %0, %1, %2;" : "=h"(r) : "f"(hi), "f"(lo));
    return r;
}
// Unpack e4m3x2 -> half2 (lower e4m3 -> lower half).
__device__ __forceinline__ __half2 cvt_h2(unsigned short s) {
    unsigned r;
    asm("cvt.rn.f16x2.e4m3x2 %0, %1;" : "=r"(r) : "h"(s));
    return *(__half2*)&r;
}

__device__ __forceinline__ void ldsm_x4(unsigned* r, unsigned addr) {
    asm volatile("ldmatrix.sync.aligned.m8n8.x4.shared.b16 {%0,%1,%2,%3}, [%4];"
                 : "=r"(r[0]), "=r"(r[1]), "=r"(r[2]), "=r"(r[3]) : "r"(addr));
}

__device__ __forceinline__ void mma_bf16(float* c, const unsigned* a, unsigned b0, unsigned b1) {
    asm volatile("mma.sync.aligned.m16n8k16.row.col.f32.bf16.bf16.f32 "
                 "{%0,%1,%2,%3}, {%4,%5,%6,%7}, {%8,%9}, {%0,%1,%2,%3};"
                 : "+f"(c[0]), "+f"(c[1]), "+f"(c[2]), "+f"(c[3])
                 : "r"(a[0]), "r"(a[1]), "r"(a[2]), "r"(a[3]), "r"(b0), "r"(b1));
}

// ---------------------------------------------------------------------------
// Kernel 1: fused node projection GEMM (both halves per block), register
// double-buffered: next k-chunk's global loads issue while current chunk's
// MMAs run, so only chunk 0's DRAM latency is exposed.
// Block: 128 rows x 256 cols, 512 threads = 16 warps.
// K chunked by 32; smem pitch 40 bf16 (80B rows) -> conflict-free ldmatrix.
// Epilogue quantizes to e4m3.
// ---------------------------------------------------------------------------
#define PITCH 40
__global__ __launch_bounds__(512) void gemm_kernel(
    const float* __restrict__ x,    // [N_NODES, 128]
    const float* __restrict__ W1,   // [128, 256] row-major
    const float* __restrict__ b1)   // [128]
{
    const int row0 = blockIdx.x * 128;
    const int tid  = threadIdx.x;
    const int lane = tid & 31;
    const int w    = tid >> 5;
    const int warp_m = w & 3;
    const int warp_n = w >> 2;

    if (blockIdx.x == 0 && tid == 0) g_loss_sum = 0.0;

    __shared__ __nv_bfloat16 As[128 * PITCH];
    __shared__ __nv_bfloat16 Bs[256 * PITCH];

    float acc[2][8][4];
#pragma unroll
    for (int mt = 0; mt < 2; mt++)
#pragma unroll
        for (int nt = 0; nt < 8; nt++)
#pragma unroll
            for (int q = 0; q < 4; q++) acc[mt][nt][q] = 0.0f;

    unsigned a_base = (unsigned)__cvta_generic_to_shared(As)
        + (unsigned)(((32 * warp_m + (lane & 15)) * PITCH + (lane >> 4) * 8) * 2);
    unsigned b_base = (unsigned)__cvta_generic_to_shared(Bs)
        + (unsigned)(((64 * warp_n + (lane & 7) + ((lane >> 4) << 3)) * PITCH
                      + ((lane >> 3) & 1) * 8) * 2);

    // Per-thread staging coordinates (fixed across chunks).
    // x: 2 float4 per thread; W: 4 float4 per thread.
    int xr_[2], xc_[2];
    int wj_[4], wc_[4];
#pragma unroll
    for (int t = 0; t < 2; t++) {
        int i = tid + 512 * t;
        xr_[t] = i >> 3; xc_[t] = i & 7;
    }
#pragma unroll
    for (int t = 0; t < 4; t++) {
        int i = tid + 512 * t;
        wj_[t] = i >> 3; wc_[t] = i & 7;
    }

    float4 xv[2], wv[4];
    // Prefetch chunk 0.
#pragma unroll
    for (int t = 0; t < 2; t++) {
        int row = row0 + xr_[t];
        xv[t] = (row < N_NODES) ? *(const float4*)(x + (size_t)row * 128 + xc_[t] * 4)
                                : make_float4(0.f, 0.f, 0.f, 0.f);
    }
#pragma unroll
    for (int t = 0; t < 4; t++) {
        int j = wj_[t] & 127;
        int koff = ((wj_[t] >> 7) << 7) + wc_[t] * 4;
        wv[t] = *(const float4*)(W1 + (size_t)j * 256 + koff);
    }

#pragma unroll
    for (int kci = 0; kci < 4; kci++) {
        // Store current chunk to smem.
#pragma unroll
        for (int t = 0; t < 2; t++)
            *(uint2*)(As + xr_[t] * PITCH + xc_[t] * 4) = cvt4(xv[t]);
#pragma unroll
        for (int t = 0; t < 4; t++)
            *(uint2*)(Bs + wj_[t] * PITCH + wc_[t] * 4) = cvt4(wv[t]);
        __syncthreads();

        // Prefetch next chunk while MMAs run.
        if (kci < 3) {
            int kc = 32 * (kci + 1);
#pragma unroll
            for (int t = 0; t < 2; t++) {
                int row = row0 + xr_[t];
                xv[t] = (row < N_NODES)
                      ? *(const float4*)(x + (size_t)row * 128 + kc + xc_[t] * 4)
                      : make_float4(0.f, 0.f, 0.f, 0.f);
            }
#pragma unroll
            for (int t = 0; t < 4; t++) {
                int j = wj_[t] & 127;
                int koff = ((wj_[t] >> 7) << 7) + kc + wc_[t] * 4;
                wv[t] = *(const float4*)(W1 + (size_t)j * 256 + koff);
            }
        }

#pragma unroll
        for (int ks = 0; ks < 2; ks++) {
            unsigned a0[4], a1[4];
            ldsm_x4(a0, a_base + ks * 32);
            ldsm_x4(a1, a_base + 16 * PITCH * 2 + ks * 32);
#pragma unroll
            for (int nt2 = 0; nt2 < 4; nt2++) {
                unsigned b[4];
                ldsm_x4(b, b_base + nt2 * 16 * PITCH * 2 + ks * 32);
                mma_bf16(acc[0][2 * nt2],     a0, b[0], b[1]);
                mma_bf16(acc[1][2 * nt2],     a1, b[0], b[1]);
                mma_bf16(acc[0][2 * nt2 + 1], a0, b[2], b[3]);
                mma_bf16(acc[1][2 * nt2 + 1], a1, b[2], b[3]);
            }
        }
        __syncthreads();
    }

    const int g = lane >> 2, t = lane & 3;
    const int col_base = (warp_n & 1) * 64;
    unsigned char* __restrict__ out = (warp_n >= 2) ? g_B8 : g_A8;

    float2 bias[8];
#pragma unroll
    for (int nt = 0; nt < 8; nt++) bias[nt] = make_float2(0.0f, 0.0f);
    if (warp_n < 2) {
#pragma unroll
        for (int nt = 0; nt < 8; nt++)
            bias[nt] = *(const float2*)(b1 + col_base + 8 * nt + 2 * t);
    }

#pragma unroll
    for (int mt = 0; mt < 2; mt++) {
        int row_lo = row0 + 32 * warp_m + 16 * mt + g;
        int row_hi = row_lo + 8;
#pragma unroll
        for (int nt = 0; nt < 8; nt++) {
            const float* c = acc[mt][nt];
            int col = col_base + 8 * nt + 2 * t;
            if (row_lo < N_NODES)
                *(unsigned short*)(out + (size_t)row_lo * DIM + col) =
                    cvt_e4m3x2(c[1] + bias[nt].y, c[0] + bias[nt].x);
            if (row_hi < N_NODES)
                *(unsigned short*)(out + (size_t)row_hi * DIM + col) =
                    cvt_e4m3x2(c[3] + bias[nt].y, c[2] + bias[nt].x);
        }
    }
}

// ---------------------------------------------------------------------------
// Kernel 2: edge phase + fused finalize. Eight threads per edge, x2 unrolled,
// with INDEX SOFTWARE PIPELINING: the next iteration's (u,v) are loaded before
// the current edges are computed, halving the pairs->gather serial chain.
// pairs is int32 (JAX x64 disabled downcasts the reference's int64).
// ---------------------------------------------------------------------------
__device__ __forceinline__ float edge_dot8(uint4 a, uint4 b, const __half2* wh) {
    const unsigned* au = (const unsigned*)&a;
    const unsigned* bu = (const unsigned*)&b;
    __half2 acc = __float2half2_rn(0.0f);
    const __half2 z2 = __float2half2_rn(0.0f);
#pragma unroll
    for (int q = 0; q < 4; q++) {
        __half2 a0 = cvt_h2((unsigned short)(au[q] & 0xFFFFu));
        __half2 a1 = cvt_h2((unsigned short)(au[q] >> 16));
        __half2 b0 = cvt_h2((unsigned short)(bu[q] & 0xFFFFu));
        __half2 b1 = cvt_h2((unsigned short)(bu[q] >> 16));
        __half2 s0 = __hmax2(__hadd2(a0, b0), z2);
        __half2 s1 = __hmax2(__hadd2(a1, b1), z2);
        acc = __hfma2(s0, wh[2 * q],     acc);
        acc = __hfma2(s1, wh[2 * q + 1], acc);
    }
    return __low2float(acc) + __high2float(acc);
}

__global__ __launch_bounds__(256) void edge_kernel(
    const int*   __restrict__ pairs,   // [2, E] int32
    const float* __restrict__ labels,  // [E]
    const float* __restrict__ W2,      // [128]
    const float* __restrict__ b2,      // [1]
    float* __restrict__ out)           // [1]
{
    const int lane = threadIdx.x & 31;
    const int sub  = lane & 7;
    const int grp  = (blockIdx.x * blockDim.x + threadIdx.x) >> 3;
    const int ngroups = (gridDim.x * blockDim.x) >> 3;

    // This thread's 16-dim slice of W2 as half2 (dims [16*sub, 16*sub+16)).
    __half2 wh[8];
#pragma unroll
    for (int q = 0; q < 8; q++) {
        float2 p = ((const float2*)W2)[8 * sub + q];
        wh[q] = __float22half2_rn(p);
    }
    const float bias2 = b2[0];

    float acc = 0.0f;

    // Software-pipelined indices: u1/v1 for edge e, u2/v2 for edge e+ngroups.
    int e = grp;
    int u1 = 0, v1 = 0, u2 = 0, v2 = 0;
    if (e < E_TOTAL)            { u1 = pairs[e];            v1 = pairs[E_TOTAL + e]; }
    if (e + ngroups < E_TOTAL)  { u2 = pairs[e + ngroups];  v2 = pairs[E_TOTAL + e + ngroups]; }

    while (e + ngroups < E_TOTAL) {
        // Gathers for the two current edges (indices already resident).
        uint4 a1 = __ldg((const uint4*)(g_A8 + (size_t)u1 * DIM + 16 * sub));
        uint4 b1 = __ldg((const uint4*)(g_B8 + (size_t)v1 * DIM + 16 * sub));
        uint4 a2 = __ldg((const uint4*)(g_A8 + (size_t)u2 * DIM + 16 * sub));
        uint4 b2v = __ldg((const uint4*)(g_B8 + (size_t)v2 * DIM + 16 * sub));
        float y1 = labels[e];
        float y2 = labels[e + ngroups];

        // Prefetch next iteration's indices (overlaps with the dot compute).
        int en = e + 2 * ngroups;
        int nu1 = 0, nv1 = 0, nu2 = 0, nv2 = 0;
        if (en < E_TOTAL)           { nu1 = pairs[en];           nv1 = pairs[E_TOTAL + en]; }
        if (en + ngroups < E_TOTAL) { nu2 = pairs[en + ngroups]; nv2 = pairs[E_TOTAL + en + ngroups]; }

        float za = edge_dot8(a1, b1, wh);
        float zb = edge_dot8(a2, b2v, wh);

        za += __shfl_xor_sync(0xFFFFFFFFu, za, 4);
        zb += __shfl_xor_sync(0xFFFFFFFFu, zb, 4);
        za += __shfl_xor_sync(0xFFFFFFFFu, za, 2);
        zb += __shfl_xor_sync(0xFFFFFFFFu, zb, 2);
        za += __shfl_xor_sync(0xFFFFFFFFu, za, 1);
        zb += __shfl_xor_sync(0xFFFFFFFFu, zb, 1);
        za += bias2;
        zb += bias2;

        float pa = __expf(-fabsf(za));
        float pb = __expf(-fabsf(zb));
        float la = fmaxf(za, 0.0f) - za * y1 + __logf(1.0f + pa);
        float lb = fmaxf(zb, 0.0f) - zb * y2 + __logf(1.0f + pb);
        if (sub == 0) acc += la + lb;

        u1 = nu1; v1 = nv1; u2 = nu2; v2 = nv2;
        e = en;
    }
    // Remainder (at most one edge; its indices are already in u1/v1).
    if (e < E_TOTAL) {
        uint4 a = __ldg((const uint4*)(g_A8 + (size_t)u1 * DIM + 16 * sub));
        uint4 b = __ldg((const uint4*)(g_B8 + (size_t)v1 * DIM + 16 * sub));
        float y = labels[e];

        float z = edge_dot8(a, b, wh);
        z += __shfl_xor_sync(0xFFFFFFFFu, z, 4);
        z += __shfl_xor_sync(0xFFFFFFFFu, z, 2);
        z += __shfl_xor_sync(0xFFFFFFFFu, z, 1);
        z += bias2;

        float p = __expf(-fabsf(z));
        float loss = fmaxf(z, 0.0f) - z * y + __logf(1.0f + p);
        if (sub == 0) acc += loss;
    }

    // Warp butterfly, block reduce, fused finalize.
#pragma unroll
    for (int off = 16; off; off >>= 1)
        acc += __shfl_xor_sync(0xFFFFFFFFu, acc, off);

    __shared__ float wsum[8];
    if (lane == 0) wsum[threadIdx.x >> 5] = acc;
    __syncthreads();
    if (threadIdx.x == 0) {
        float s = 0.0f;
#pragma unroll
        for (int i = 0; i < 8; i++) s += wsum[i];
        atomicAdd(&g_loss_sum, (double)s);
        __threadfence();
        if (atomicAdd(&g_done, 1u) == gridDim.x - 1) {
            g_done = 0;  // reset for next graph replay
            out[0] = (float)(g_loss_sum / (double)E_TOTAL);
        }
    }
}

// ---------------------------------------------------------------------------
// kernel_launch — input order: x, W1, b1, W2, b2, labels, pairs
// ---------------------------------------------------------------------------
extern "C" void kernel_launch(void* const* d_in, const int* in_sizes, int n_in,
                              void* d_out, int out_size) {
    const float* x      = (const float*)d_in[0];
    const float* W1     = (const float*)d_in[1];
    const float* b1     = (const float*)d_in[2];
    const float* W2     = (const float*)d_in[3];
    const float* b2     = (const float*)d_in[4];
    const float* labels = (const float*)d_in[5];
    const int*   pairs  = (const int*)d_in[6];
    float* out = (float*)d_out;

    gemm_kernel<<<ROW_BLOCKS, 512>>>(x, W1, b1);

    edge_kernel<<<1184, 256>>>(pairs, labels, W2, b2, out);
}